// round 5
// baseline (speedup 1.0000x reference)
#include <cuda_runtime.h>

#define HID 128
#define HEADS 4
#define DIM 32
#define NT 8
#define ETY 8

#define N_SRC_MAX 200000
#define N_CTR_MAX 100000
#define N_EDGE_MAX 800000
#define OSRC_LEN (N_SRC_MAX + 1024)
#define ODST_LEN (N_CTR_MAX + 1024)

typedef unsigned long long u64;

__device__ __forceinline__ u64 pk2(float x, float y) {
    u64 r; asm("mov.b64 %0,{%1,%2};" : "=l"(r) : "f"(x), "f"(y)); return r;
}
__device__ __forceinline__ void up2(float& x, float& y, u64 v) {
    asm("mov.b64 {%0,%1},%2;" : "=f"(x), "=f"(y) : "l"(v));
}
__device__ __forceinline__ u64 f2fma(u64 a, u64 b, u64 c) {
    u64 d; asm("fma.rn.f32x2 %0,%1,%2,%3;" : "=l"(d) : "l"(a), "l"(b), "l"(c)); return d;
}

// ---------------- scratch (device globals; no runtime allocation) ----------------
__device__ float g_k[(size_t)N_SRC_MAX * HID];
__device__ float g_v[(size_t)N_SRC_MAX * HID];
__device__ float g_q[(size_t)N_CTR_MAX * HID];
__device__ float g_a[(size_t)N_EDGE_MAX * HEADS];   // edge scores
__device__ int   g_dstid[N_EDGE_MAX];
__device__ int   g_eord[N_EDGE_MAX];
__device__ int   g_osrc[OSRC_LEN];
__device__ int   g_odst[ODST_LEN];
__device__ int   g_cnt[16];
__device__ int   g_pos[16];
__device__ int   g_ecnt[8];
__device__ int   g_epos[8];

// ---------------- prep ----------------
__global__ void init_kernel() {
    int i = blockIdx.x * blockDim.x + threadIdx.x;
    int stride = gridDim.x * blockDim.x;
    if (i < 16) { g_cnt[i] = 0; g_pos[i] = 0; }
    if (i < 8)  { g_ecnt[i] = 0; g_epos[i] = 0; }
    for (int j = i; j < OSRC_LEN; j += stride) g_osrc[j] = -1;
    for (int j = i; j < ODST_LEN; j += stride) g_odst[j] = -1;
}

// combined node + edge histogram
__global__ void hist_all_kernel(const int* __restrict__ ntype, const int* __restrict__ etype,
                                int num_src, int num_center, int num_edge) {
    __shared__ int sc[24];
    if (threadIdx.x < 24) sc[threadIdx.x] = 0;
    __syncthreads();
    int n = blockIdx.x * blockDim.x + threadIdx.x;
    if (n < num_src) {
        int t = ntype[n];
        atomicAdd(&sc[t], 1);
        if (n < num_center) atomicAdd(&sc[8 + t], 1);
    }
    if (n < num_edge) atomicAdd(&sc[16 + etype[n]], 1);
    __syncthreads();
    if (threadIdx.x < 16 && sc[threadIdx.x]) atomicAdd(&g_cnt[threadIdx.x], sc[threadIdx.x]);
    if (threadIdx.x >= 16 && threadIdx.x < 24 && sc[threadIdx.x])
        atomicAdd(&g_ecnt[threadIdx.x - 16], sc[threadIdx.x]);
}

__global__ void offsets_kernel() {
    if (threadIdx.x == 0 && blockIdx.x == 0) {
        int off = 0;
        for (int t = 0; t < 8; t++) { g_pos[t] = off; off += ((g_cnt[t] + 63) >> 6) << 6; }
        off = 0;
        for (int t = 0; t < 8; t++) { g_pos[8 + t] = off; off += ((g_cnt[8 + t] + 63) >> 6) << 6; }
        off = 0;
        for (int t = 0; t < 8; t++) { g_epos[t] = off; off += g_ecnt[t]; }
    }
}

// combined node + edge scatter
__global__ void scatter_all_kernel(const int* __restrict__ ntype, const int* __restrict__ etype,
                                   int num_src, int num_center, int num_edge) {
    __shared__ int sc[24];
    __shared__ int sb[24];
    if (threadIdx.x < 24) sc[threadIdx.x] = 0;
    __syncthreads();
    int n = blockIdx.x * blockDim.x + threadIdx.x;
    int t = 0, r1 = -1, r2 = -1;
    int te = 0, re = -1;
    if (n < num_src) {
        t = ntype[n];
        r1 = atomicAdd(&sc[t], 1);
        if (n < num_center) r2 = atomicAdd(&sc[8 + t], 1);
    }
    if (n < num_edge) { te = etype[n]; re = atomicAdd(&sc[16 + te], 1); }
    __syncthreads();
    if (threadIdx.x < 16)
        sb[threadIdx.x] = sc[threadIdx.x] ? atomicAdd(&g_pos[threadIdx.x], sc[threadIdx.x]) : 0;
    else if (threadIdx.x < 24)
        sb[threadIdx.x] = sc[threadIdx.x] ? atomicAdd(&g_epos[threadIdx.x - 16], sc[threadIdx.x]) : 0;
    __syncthreads();
    if (r1 >= 0) g_osrc[sb[t] + r1] = n;
    if (r2 >= 0) g_odst[sb[8 + t] + r2] = n;
    if (re >= 0) g_eord[sb[16 + te] + re] = n;
}

// ---------------- typed node projection: dense GEMM on sorted tiles (f32x2) ----------------
__global__ void __launch_bounds__(256, 2) node_gemm_kernel(
    const float* __restrict__ x, const float* __restrict__ W8,
    const int* __restrict__ ntype, int which)
{
    extern __shared__ float sm[];
    float* w_sm = sm;              // 128*128
    float* xT = sm + 128 * 128;    // 128*64 (transposed x tile, m fastest)
    const int* order = (which == 2) ? g_odst : g_osrc;
    float* outp = (which == 0) ? g_k : (which == 1) ? g_v : g_q;

    const int base = blockIdx.x * 64;
    int n0 = order[base];
    if (n0 < 0) return;
    int t = ntype[n0];
    const int tid = threadIdx.x;

    const float4* W4 = (const float4*)(W8 + (size_t)t * 128 * 128);
    float4* w4 = (float4*)w_sm;
#pragma unroll
    for (int i = 0; i < 16; ++i) w4[tid + 256 * i] = W4[tid + 256 * i];

    int m = tid >> 2, q4 = tid & 3;
    int row = order[base + m];
#pragma unroll
    for (int it = 0; it < 8; ++it) {
        int c = q4 * 4 + it * 16;
        float4 xv = make_float4(0.f, 0.f, 0.f, 0.f);
        if (row >= 0) xv = *(const float4*)(x + (size_t)row * 128 + c);
        xT[(c + 0) * 64 + m] = xv.x;
        xT[(c + 1) * 64 + m] = xv.y;
        xT[(c + 2) * 64 + m] = xv.z;
        xT[(c + 3) * 64 + m] = xv.w;
    }
    __syncthreads();

    const int tm = tid >> 5;
    const int tn = tid & 31;
    u64 acc2[4][4];
#pragma unroll
    for (int i = 0; i < 4; ++i)
#pragma unroll
        for (int j = 0; j < 4; ++j) acc2[i][j] = 0ull;

#pragma unroll 8
    for (int kk = 0; kk < 128; ++kk) {
        const ulonglong2* xp = (const ulonglong2*)(xT + kk * 64 + tm * 8);
        ulonglong2 xa = xp[0];
        ulonglong2 xb = xp[1];
        u64 xs[4] = { xa.x, xa.y, xb.x, xb.y };
        float4 wv = *(const float4*)(w_sm + kk * 128 + tn * 4);
        u64 wd[4] = { pk2(wv.x, wv.x), pk2(wv.y, wv.y), pk2(wv.z, wv.z), pk2(wv.w, wv.w) };
#pragma unroll
        for (int i = 0; i < 4; ++i)
#pragma unroll
            for (int j = 0; j < 4; ++j) acc2[i][j] = f2fma(xs[i], wd[j], acc2[i][j]);
    }

#pragma unroll
    for (int i2 = 0; i2 < 4; ++i2) {
        float r0[4], r1[4];
#pragma unroll
        for (int j = 0; j < 4; ++j) up2(r0[j], r1[j], acc2[i2][j]);
        int m0 = tm * 8 + 2 * i2;
        int ra = order[base + m0], rb = order[base + m0 + 1];
        if (ra >= 0) *(float4*)(outp + (size_t)ra * 128 + tn * 4) = make_float4(r0[0], r0[1], r0[2], r0[3]);
        if (rb >= 0) *(float4*)(outp + (size_t)rb * 128 + tn * 4) = make_float4(r1[0], r1[1], r1[2], r1[3]);
    }
}

// ---------------- dst id fill ----------------
__global__ void fill_dst_kernel(const int* __restrict__ ptr, int C) {
    int c = blockIdx.x * blockDim.x + threadIdx.x;
    if (c >= C) return;
    int e0 = ptr[c], e1 = ptr[c + 1];
    for (int e = e0; e < e1; ++e) g_dstid[e] = c;
}

// ---------------- edge scores: lane-per-edge, etype-sorted ----------------
__global__ void __launch_bounds__(512, 1) scores_kernel(
    const int* __restrict__ idx, const int* __restrict__ etype,
    const float* __restrict__ a_rel, const float* __restrict__ relptr, int E)
{
    extern __shared__ float A_sm[];   // 128KB
    __shared__ float rp[32];
    for (int i = threadIdx.x; i < ETY * HEADS * DIM * DIM; i += blockDim.x) A_sm[i] = a_rel[i];
    if (threadIdx.x < 32) rp[threadIdx.x] = relptr[threadIdx.x];
    __syncthreads();

    const float inv = 0.17677669529663689f; // 1/sqrt(32)
    int stride = gridDim.x * blockDim.x;
    for (int p = blockIdx.x * blockDim.x + threadIdx.x; p < E; p += stride) {
        int e = g_eord[p];
        int s = idx[e];
        int et = etype[e];
        int c = g_dstid[e];
        const float4* kp = (const float4*)(g_k + (size_t)s * HID);
        const ulonglong2* qp = (const ulonglong2*)(g_q + (size_t)c * HID);
        const float* Ab = A_sm + et * (HEADS * DIM * DIM);
        float outv[4];
#pragma unroll 1
        for (int h = 0; h < 4; ++h) {
            u64 kw2[16];
#pragma unroll
            for (int i = 0; i < 16; ++i) kw2[i] = 0ull;
            const ulonglong2* Ar = (const ulonglong2*)(Ab + h * 1024);
#pragma unroll 1
            for (int dg = 0; dg < 8; ++dg) {
                float4 kv = kp[h * 8 + dg];
                float kd[4] = { kv.x, kv.y, kv.z, kv.w };
#pragma unroll
                for (int j = 0; j < 4; ++j) {
                    u64 kd2 = pk2(kd[j], kd[j]);
                    const ulonglong2* A2 = Ar + (size_t)(dg * 4 + j) * 8;
#pragma unroll
                    for (int f = 0; f < 8; ++f) {
                        ulonglong2 aa = A2[f];
                        kw2[2 * f]     = f2fma(kd2, aa.x, kw2[2 * f]);
                        kw2[2 * f + 1] = f2fma(kd2, aa.y, kw2[2 * f + 1]);
                    }
                }
            }
            u64 acc = 0ull;
#pragma unroll
            for (int f = 0; f < 8; ++f) {
                ulonglong2 qq = qp[h * 8 + f];
                acc = f2fma(kw2[2 * f], qq.x, acc);
                acc = f2fma(kw2[2 * f + 1], qq.y, acc);
            }
            float lo, hi; up2(lo, hi, acc);
            outv[h] = (lo + hi) * rp[h * ETY + et] * inv;
        }
        *(float4*)(g_a + (size_t)e * 4) = make_float4(outv[0], outv[1], outv[2], outv[3]);
    }
}

// ---------------- fused softmax + type-rescan aggregation: warp per center ----------------
// For each present type t: rescan segment, accumulate s[h] = sum alpha*v (4 regs),
// flush through 32x32 matvec with m_rel[t]. No wide accumulator -> no spills.
__global__ void __launch_bounds__(1024, 1) fused_agg_kernel(
    const int* __restrict__ ptr, const int* __restrict__ idx,
    const int* __restrict__ etype, const float* __restrict__ m_rel,
    float* __restrict__ out, int C)
{
    extern __shared__ float M_sm[];   // [8][4][32][32] = 128KB
    for (int i = threadIdx.x; i < ETY * HEADS * DIM * DIM; i += blockDim.x) M_sm[i] = m_rel[i];
    __syncthreads();

    const unsigned FULL = 0xffffffffu;
    const int lane = threadIdx.x & 31;
    const int w0 = (blockIdx.x * blockDim.x + threadIdx.x) >> 5;
    const int nw = (gridDim.x * blockDim.x) >> 5;

    for (int c = w0; c < C; c += nw) {
        int e0 = ptr[c], e1 = ptr[c + 1];
        float* ob = out + (size_t)c * HID;
        if (e1 <= e0) {
            ob[lane] = 0.f; ob[32 + lane] = 0.f; ob[64 + lane] = 0.f; ob[96 + lane] = 0.f;
            continue;
        }
        int deg = e1 - e0;

        // softmax stats (lane layout: h = lane&3, el = lane>>2)
        int h4 = lane & 3, el = lane >> 2;
        float mx = __int_as_float(0xff800000);
        for (int i = el; i < deg; i += 8) mx = fmaxf(mx, g_a[(size_t)(e0 + i) * 4 + h4]);
        mx = fmaxf(mx, __shfl_xor_sync(FULL, mx, 4));
        mx = fmaxf(mx, __shfl_xor_sync(FULL, mx, 8));
        mx = fmaxf(mx, __shfl_xor_sync(FULL, mx, 16));
        float den = 0.f;
        for (int i = el; i < deg; i += 8) den += __expf(g_a[(size_t)(e0 + i) * 4 + h4] - mx);
        den += __shfl_xor_sync(FULL, den, 4);
        den += __shfl_xor_sync(FULL, den, 8);
        den += __shfl_xor_sync(FULL, den, 16);
        float dinv = 1.f / den;
        float mxh[4], dih[4];
#pragma unroll
        for (int hh = 0; hh < 4; ++hh) {
            mxh[hh] = __shfl_sync(FULL, mx, hh);
            dih[hh] = __shfl_sync(FULL, dinv, hh);
        }

        // present-type mask
        unsigned tm = 0u;
        for (int i = lane; i < deg; i += 32) tm |= (1u << etype[e0 + i]);
        tm = __reduce_or_sync(FULL, tm);

        float o0 = 0.f, o1 = 0.f, o2 = 0.f, o3 = 0.f;
#pragma unroll 1
        for (int t = 0; t < 8; ++t) {
            if (!((tm >> t) & 1u)) continue;
            float s0 = 0.f, s1 = 0.f, s2 = 0.f, s3 = 0.f;
            for (int e = e0; e < e1; ++e) {
                if (etype[e] != t) continue;            // warp-uniform branch
                float4 av = *(const float4*)(g_a + (size_t)e * 4);  // broadcast
                const float* vb = g_v + (size_t)idx[e] * HID;
                s0 = fmaf(__expf(av.x - mxh[0]) * dih[0], vb[lane],      s0);
                s1 = fmaf(__expf(av.y - mxh[1]) * dih[1], vb[32 + lane], s1);
                s2 = fmaf(__expf(av.z - mxh[2]) * dih[2], vb[64 + lane], s2);
                s3 = fmaf(__expf(av.w - mxh[3]) * dih[3], vb[96 + lane], s3);
            }
            const float* Mb = M_sm + t * (HEADS * DIM * DIM);   // [h][d'][d]
#pragma unroll
            for (int dp = 0; dp < 32; ++dp) {
                float b0 = __shfl_sync(FULL, s0, dp);
                float b1 = __shfl_sync(FULL, s1, dp);
                float b2 = __shfl_sync(FULL, s2, dp);
                float b3 = __shfl_sync(FULL, s3, dp);
                o0 = fmaf(b0, Mb[(0 * 32 + dp) * 32 + lane], o0);
                o1 = fmaf(b1, Mb[(1 * 32 + dp) * 32 + lane], o1);
                o2 = fmaf(b2, Mb[(2 * 32 + dp) * 32 + lane], o2);
                o3 = fmaf(b3, Mb[(3 * 32 + dp) * 32 + lane], o3);
            }
        }
        ob[lane]      = o0;
        ob[32 + lane] = o1;
        ob[64 + lane] = o2;
        ob[96 + lane] = o3;
    }
}

// ---------------- host launcher ----------------
extern "C" void kernel_launch(void* const* d_in, const int* in_sizes, int n_in,
                              void* d_out, int out_size)
{
    (void)out_size;
    const float* x     = (const float*)d_in[0];
    const int*   ptr   = (const int*)d_in[1];
    const int*   idx   = (const int*)d_in[2];
    const int*   ntype = (const int*)d_in[3];
    const int*   etype = (const int*)d_in[4];
    int wb = n_in - 6;
    const float* k_lin = (const float*)d_in[wb + 0];
    const float* q_lin = (const float*)d_in[wb + 1];
    const float* v_lin = (const float*)d_in[wb + 2];
    const float* a_rel = (const float*)d_in[wb + 3];
    const float* m_rel = (const float*)d_in[wb + 4];
    const float* relp  = (const float*)d_in[wb + 5];

    int num_src    = in_sizes[3];
    int num_edge   = in_sizes[2];
    int num_center = in_sizes[1] - 1;
    float* out = (float*)d_out;

    cudaFuncSetAttribute(node_gemm_kernel, cudaFuncAttributeMaxDynamicSharedMemorySize, 98304);
    cudaFuncSetAttribute(scores_kernel,    cudaFuncAttributeMaxDynamicSharedMemorySize, 131072);
    cudaFuncSetAttribute(fused_agg_kernel, cudaFuncAttributeMaxDynamicSharedMemorySize, 131072);

    int nmax = num_edge > num_src ? num_edge : num_src;
    init_kernel<<<600, 512>>>();
    hist_all_kernel<<<(nmax + 255) / 256, 256>>>(ntype, etype, num_src, num_center, num_edge);
    offsets_kernel<<<1, 32>>>();
    scatter_all_kernel<<<(nmax + 255) / 256, 256>>>(ntype, etype, num_src, num_center, num_edge);
    fill_dst_kernel<<<(num_center + 255) / 256, 256>>>(ptr, num_center);

    int tiles_src = (num_src + 63) / 64 + 8;
    int tiles_dst = (num_center + 63) / 64 + 8;
    node_gemm_kernel<<<tiles_src, 256, 98304>>>(x, k_lin, ntype, 0);
    node_gemm_kernel<<<tiles_src, 256, 98304>>>(x, v_lin, ntype, 1);
    node_gemm_kernel<<<tiles_dst, 256, 98304>>>(x, q_lin, ntype, 2);

    scores_kernel<<<148, 512, 131072>>>(idx, etype, a_rel, relp, num_edge);
    fused_agg_kernel<<<148, 1024, 131072>>>(ptr, idx, etype, m_rel, out, num_center);
}